// round 12
// baseline (speedup 1.0000x reference)
#include <cuda_runtime.h>
#include <cstdint>
#include <climits>
#include <cfloat>
#include <math.h>

#define VOCAB 128000
#define BATCH 256
#define SEG 8
#define SEGLEN (VOCAB / SEG)          // 16000
#define THR 256
#define NQ (SEGLEN / 4)               // 4000 float4 per segment
#define NIT ((NQ + THR - 1) / THR)    // 16
#define CAP 16384
#define FINE 1024

#define NEGINF_F __int_as_float(0xFF800000)
#define POSINF_F __int_as_float(0x7F800000)

// okey-space bounds of finite floats
#define KLO 0x00800000u               // okey(-FLT_MAX)
#define KHI 0xFF800000u               // okey(FLT_MAX)+1

// ---------------- scratch ----------------
__device__ unsigned long long g_packMax[BATCH];   // (okey(x)<<32) | ~idx
__device__ float              g_hist[BATCH][4096];
__device__ int                g_B1[BATCH];
__device__ float              g_A1[BATCH];
__device__ float              g_T[BATCH];
__device__ int                g_done[BATCH];
__device__ float              g_xLo[BATCH], g_xHi[BATCH];     // raw-x interval of bin B1
__device__ float              g_xGT[BATCH], g_xEq[BATCH];     // raw-x thresholds for kept test
__device__ int                g_tieMin[BATCH];
__device__ int                g_candCnt[BATCH];
__device__ float              g_cs[BATCH][CAP];
__device__ int                g_ci[BATCH][CAP];
__device__ float              g_keptE[BATCH];                 // exact, accumulated in k4
__device__ unsigned long long g_bestPack[BATCH];  // (okey(e/w)<<32) | ~idx
__device__ int                g_arrM[BATCH], g_arr3[BATCH], g_arr4[BATCH];

// ---------------- helpers ----------------
__device__ __forceinline__ unsigned okey(float s) {
    unsigned bb = __float_as_uint(s);
    return (bb & 0x80000000u) ? ~bb : (bb | 0x80000000u);
}
__device__ __forceinline__ float okey_decode(unsigned k) {
    return __uint_as_float((k & 0x80000000u) ? (k & 0x7FFFFFFFu) : ~k);
}
__device__ __forceinline__ float bin_upper(unsigned bin) {
    return okey_decode((bin << 20) | 0x000FFFFFu);
}
__device__ __forceinline__ unsigned rotl32(unsigned x, int r) { return __funnelshift_l(x, x, r); }

// JAX partitionable threefry2x32, key (0,42): x0=0, x1=i+42, 20 rounds, bits=x0^x1.
// Returns w = -log(u), u = max(tiny, mantissa-uniform). Precise logf.
__device__ __forceinline__ float w_at(unsigned i) {
    unsigned x0 = 0u;
    unsigned x1 = i + 42u;
#define TFR(r) { x0 += x1; x1 = rotl32(x1, r); x1 ^= x0; }
    TFR(13) TFR(15) TFR(26) TFR(6)   x0 += 42u;          x1 += 0x1BD11BF1u;
    TFR(17) TFR(29) TFR(16) TFR(24)  x0 += 0x1BD11BF0u;  x1 += 2u;
    TFR(13) TFR(15) TFR(26) TFR(6)   /* +0 */            x1 += 45u;
    TFR(17) TFR(29) TFR(16) TFR(24)  x0 += 42u;          x1 += 0x1BD11BF4u;
    TFR(13) TFR(15) TFR(26) TFR(6)   x0 += 0x1BD11BF0u;  x1 += 5u;
#undef TFR
    unsigned bits = x0 ^ x1;
    float f = __uint_as_float((bits >> 9) | 0x3f800000u) - 1.0f;
    float u = fmaxf(f, 1.17549435e-38f);
    return -logf(u);
}

__device__ __forceinline__ float row_rcp(float t) {
    float tt = (t == 0.f) ? 1.f : t;
    return __fdiv_rn(1.0f, tt);
}
__device__ __forceinline__ float row_smax(int b, float rcp) {
    unsigned hk = (unsigned)(g_packMax[b] >> 32);
    return okey_decode(hk) * rcp;
}

// ---------------- K0: zero scratch ----------------
__global__ void k0_init() {
    int i = blockIdx.x * blockDim.x + threadIdx.x;   // BATCH*4096 threads
    ((float*)g_hist)[i] = 0.f;
    if (i < BATCH) {
        g_packMax[i] = 0ull; g_keptE[i] = 0.f;
        g_bestPack[i] = 0ull; g_candCnt[i] = 0;
        g_arrM[i] = 0; g_arr3[i] = 0; g_arr4[i] = 0;
    }
}

// ---------------- KM: max/argmax + bin-local-ref histogram ; last block: select + B1 preimage ----------------
__global__ void kM_maxhist(const float* __restrict__ logits, const float* __restrict__ temps,
                           const float* __restrict__ topps) {
    int b = blockIdx.y, seg = blockIdx.x, tid = threadIdx.x;
    __shared__ float h[4096];
    for (int i = tid; i < 4096; i += THR) h[i] = 0.f;
    float rcp = row_rcp(temps[b]);
    __syncthreads();
    const float4* row4 = (const float4*)(logits + (size_t)b * VOCAB + seg * SEGLEN);
    int lo = seg * SEGLEN;
    float m = -INFINITY; int mi = 0;
    for (int i = tid; i < NQ; i += THR) {
        float4 x = row4[i];
        int v = lo + 4 * i;
        #pragma unroll
        for (int j = 0; j < 4; j++) {
            float xv = (j == 0) ? x.x : (j == 1) ? x.y : (j == 2) ? x.z : x.w;
            if (xv > m) { m = xv; mi = v + j; }
            float s = xv * rcp;
            unsigned bin = okey(s) >> 20;
            float e = __expf(s - bin_upper(bin));     // bin-local reference
            atomicAdd(&h[bin], e);
        }
    }
    __shared__ unsigned long long sp[THR];
    sp[tid] = ((unsigned long long)okey(m) << 32) | (unsigned)(~mi);
    __syncthreads();
    for (int s = THR / 2; s > 0; s >>= 1) {
        if (tid < s) sp[tid] = max(sp[tid], sp[tid + s]);
        __syncthreads();
    }
    if (tid == 0) atomicMax(&g_packMax[b], sp[0]);
    for (int i = tid; i < 4096; i += THR) if (h[i] != 0.f) atomicAdd(&g_hist[b][i], h[i]);

    // ----- last-block-per-row: rescale + level-1 select + B1 raw-x preimage -----
    __threadfence();
    __shared__ int s_last;
    if (tid == 0) s_last = (atomicAdd(&g_arrM[b], 1) == SEG - 1);
    __syncthreads();
    if (!s_last) return;
    __threadfence();
    float smax = row_smax(b, rcp);
    for (int i = tid; i < 4096; i += THR) {
        float hv = g_hist[b][i];
        h[i] = (hv > 0.f) ? hv * __expf(bin_upper((unsigned)i) - smax) : 0.f;
    }
    __shared__ float warpSum[8], warpEx[8];
    __shared__ float s_T;
    __shared__ int s_seg, s_B1v;
    if (tid == 0) s_seg = THR;
    __syncthreads();
    float part = 0.f;
    #pragma unroll
    for (int jj = 0; jj < 16; jj++) part += h[4095 - (tid * 16 + jj)];
    int lane = tid & 31, wid = tid >> 5;
    float sc = part;
    for (int o = 1; o < 32; o <<= 1) { float v = __shfl_up_sync(~0u, sc, o); if (lane >= o) sc += v; }
    float ex = sc - part;
    if (lane == 31) warpSum[wid] = sc;
    __syncthreads();
    if (tid == 0) {
        float Z = 0.f;
        #pragma unroll
        for (int s = 0; s < 8; s++) Z += warpSum[s];
        float p = topps[b]; p = fminf(fmaxf(p, 0.f), 1.f);
        s_T = p * Z;
    }
    if (wid == 0) {
        float ws = (lane < 8) ? warpSum[lane] : 0.f;
        float s2 = ws;
        for (int o = 1; o < 8; o <<= 1) { float v = __shfl_up_sync(0xFFFFFFFFu, s2, o); if (lane >= o) s2 += v; }
        if (lane < 8) warpEx[lane] = s2 - ws;
    }
    __syncthreads();
    float T = s_T;
    float P = ex + warpEx[wid];
    bool flag = (part > 0.f) && (P + part > T);
    if (flag) atomicMin(&s_seg, tid);
    __syncthreads();
    if (tid == s_seg) {
        float cum = P;
        for (int jj = 0; jj < 16; jj++) {
            int bin = 4095 - (tid * 16 + jj); float hh = h[bin];
            if (hh > 0.f && cum + hh > T) { s_B1v = bin; g_A1[b] = cum; break; }
            cum += hh;
        }
    }
    __syncthreads();
    if (tid == 0) {
        g_T[b] = T;
        if (s_seg == THR) {                    // all kept
            g_done[b] = 1; g_tieMin[b] = INT_MIN;
            g_xGT[b] = -FLT_MAX; g_xEq[b] = -FLT_MAX;   // kept: x >= -FLT_MAX (pad -inf fails)
        } else {
            g_done[b] = 0; g_B1[b] = s_B1v;
            int B1 = s_B1v;
            // binary search raw-x preimage of bin B1 (monotone in okey space)
            unsigned a = KLO, bnd = KHI;
            while (a < bnd) {                  // first k: bin(decode(k)*rcp) >= B1
                unsigned mid = a + (bnd - a) / 2;
                int bb = (int)(okey(okey_decode(mid) * rcp) >> 20);
                if (bb >= B1) bnd = mid; else a = mid + 1;
            }
            unsigned kA = a;
            a = kA; bnd = KHI;
            while (a < bnd) {                  // first k: bin > B1
                unsigned mid = a + (bnd - a) / 2;
                int bb = (int)(okey(okey_decode(mid) * rcp) >> 20);
                if (bb > B1) bnd = mid; else a = mid + 1;
            }
            unsigned kB = a;
            g_xLo[b] = (kA < KHI) ? okey_decode(kA) : POSINF_F;
            g_xHi[b] = (kB < KHI) ? okey_decode(kB) : POSINF_F;   // exclusive
        }
    }
}

// ---------------- K3g: gather bin-B1 members (raw interval test) ; last block: select2 + walk + kept preimage ----------------
__global__ void k3g_gather(const float* __restrict__ logits, const float* __restrict__ temps) {
    int b = blockIdx.y;
    if (g_done[b]) return;
    int seg = blockIdx.x, tid = threadIdx.x;
    float rcp = row_rcp(temps[b]);
    float smax = row_smax(b, rcp);
    float xLo = g_xLo[b], xHi = g_xHi[b];
    const float4* row4 = (const float4*)(logits + (size_t)b * VOCAB + seg * SEGLEN);
    int lo = seg * SEGLEN;
    for (int i = tid; i < NQ; i += THR) {
        float4 x = row4[i];
        int v = lo + 4 * i;
        #pragma unroll
        for (int j = 0; j < 4; j++) {
            float xv = (j == 0) ? x.x : (j == 1) ? x.y : (j == 2) ? x.z : x.w;
            if (xv >= xLo && xv < xHi) {
                float s = xv * rcp;
                int pos = atomicAdd(&g_candCnt[b], 1);
                if (pos < CAP) { g_cs[b][pos] = s; g_ci[b][pos] = v + j; }
            }
        }
    }

    // ----- last-block-per-row: level-2 select + fine tie walk + kept raw-x preimage -----
    __threadfence();
    __shared__ int s_last;
    if (tid == 0) s_last = (atomicAdd(&g_arr3[b], 1) == SEG - 1);
    __syncthreads();
    if (!s_last) return;
    __threadfence();

    __shared__ float h[4096];
    __shared__ float warpSum[8], warpEx[8];
    __shared__ int s_seg, s_B2;
    __shared__ float s_A2;
    __shared__ float fs[FINE];
    __shared__ int   fi[FINE];
    __shared__ int   fcnt;
    for (int i = tid; i < 4096; i += THR) h[i] = 0.f;
    if (tid == 0) { fcnt = 0; s_seg = THR; }
    __syncthreads();
    int n = min(g_candCnt[b], CAP);
    for (int i = tid; i < n; i += THR) {
        float s = g_cs[b][i];
        atomicAdd(&h[(okey(s) >> 8) & 0xFFFu], __expf(s - smax));
    }
    __syncthreads();
    float T = g_T[b], A1 = g_A1[b];
    float part = 0.f;
    #pragma unroll
    for (int jj = 0; jj < 16; jj++) part += h[4095 - (tid * 16 + jj)];
    int lane = tid & 31, wid = tid >> 5;
    float sc = part;
    for (int o = 1; o < 32; o <<= 1) { float v = __shfl_up_sync(~0u, sc, o); if (lane >= o) sc += v; }
    float ex = sc - part;
    if (lane == 31) warpSum[wid] = sc;
    __syncthreads();
    if (wid == 0) {
        float ws = (lane < 8) ? warpSum[lane] : 0.f;
        float s2 = ws;
        for (int o = 1; o < 8; o <<= 1) { float v = __shfl_up_sync(0xFFFFFFFFu, s2, o); if (lane >= o) s2 += v; }
        if (lane < 8) warpEx[lane] = s2 - ws;
    }
    __syncthreads();
    float P = A1 + ex + warpEx[wid];
    bool flag = (part > 0.f) && (P + part > T);
    if (flag) atomicMin(&s_seg, tid);
    __syncthreads();
    if (tid == s_seg) {
        float cum = P;
        for (int jj = 0; jj < 16; jj++) {
            int bin = 4095 - (tid * 16 + jj); float hh = h[bin];
            if (hh > 0.f && cum + hh > T) { s_B2 = bin; s_A2 = cum; break; }
            cum += hh;
        }
    }
    if (tid == 0 && s_seg == THR) {   // rounding edge: lowest nonempty sub-bin
        float cum = A1; int last = -1; float lastA = A1;
        for (int j = 0; j < 4096; j++) {
            int bin = 4095 - j; float hh = h[bin];
            if (hh > 0.f) { last = bin; lastA = cum; }
            cum += hh;
        }
        s_B2 = last; s_A2 = lastA;
    }
    __syncthreads();
    unsigned pref = ((unsigned)g_B1[b] << 12) | (unsigned)s_B2;
    float A2 = s_A2;
    for (int i = tid; i < n; i += THR) {
        float s = g_cs[b][i];
        if ((okey(s) >> 8) == pref) {
            int pos = atomicAdd(&fcnt, 1);
            if (pos < FINE) { fs[pos] = s; fi[pos] = g_ci[b][i]; }
        }
    }
    __syncthreads();
    if (tid == 0) {
        int m = min(fcnt, FINE);
        for (int i = 1; i < m; i++) {       // desc by (value desc, index desc)
            float sv = fs[i]; int iv = fi[i]; int j = i - 1;
            while (j >= 0 && (fs[j] < sv || (fs[j] == sv && fi[j] < iv))) {
                fs[j + 1] = fs[j]; fi[j + 1] = fi[j]; j--;
            }
            fs[j + 1] = sv; fi[j + 1] = iv;
        }
        bool globalFirst = (A2 == 0.f);     // rank-0 always kept
        float cum = A2; int lastKept = -1;
        for (int i = 0; i < m; i++) {
            cum += __expf(fs[i] - smax);
            bool kept = (cum <= T) || (globalFirst && i == 0);
            if (kept) lastKept = i; else break;
        }
        float vb; int tieMin;
        if (lastKept < 0) {
            vb = fs[0]; tieMin = INT_MAX;
        } else {
            float vL = fs[lastKept];
            bool partial = (lastKept + 1 < m) && (fs[lastKept + 1] == vL);
            vb = vL;
            tieMin = partial ? fi[lastKept] : INT_MIN;
        }
        g_tieMin[b] = tieMin;
        // raw-x preimage of {s >= vb} and {s > vb}
        unsigned a = KLO, bnd = KHI;
        while (a < bnd) {                   // first k: decode(k)*rcp >= vb
            unsigned mid = a + (bnd - a) / 2;
            if (okey_decode(mid) * rcp >= vb) bnd = mid; else a = mid + 1;
        }
        unsigned kC = a;
        a = kC; bnd = KHI;
        while (a < bnd) {                   // first k: decode(k)*rcp > vb
            unsigned mid = a + (bnd - a) / 2;
            if (okey_decode(mid) * rcp > vb) bnd = mid; else a = mid + 1;
        }
        unsigned kD = a;
        g_xEq[b] = (kC < KHI) ? okey_decode(kC) : POSINF_F;
        g_xGT[b] = (kD < KHI) ? okey_decode(kD) : POSINF_F;
    }
}

// ---------------- K4: raw-threshold kept test + exact keptE + compacted gumbel argmax ----------------
__global__ void k4_sample(const float* __restrict__ logits, const float* __restrict__ temps,
                          float* __restrict__ out, int half_out) {
    int b = blockIdx.y, seg = blockIdx.x, tid = threadIdx.x;
    int lane = tid & 31, wrp = tid >> 5;
    float t = temps[b];
    float rcp = row_rcp(t);
    float smax = row_smax(b, rcp);
    float xGT = g_xGT[b], xEq = g_xEq[b];
    int tieMin = g_tieMin[b];
    bool greedy = (t == 0.f);
    const float4* row4 = (const float4*)(logits + (size_t)b * VOCAB + seg * SEGLEN);
    int lo = seg * SEGLEN;
    unsigned rowbase = (unsigned)b * (unsigned)VOCAB;

    __shared__ float ebuf[8][64];
    __shared__ int   ibuf[8][64];
    float keptE = 0.f;
    float be = 0.f, bw = 1.f; int bi = INT_MAX;   // best = (e, w, idx); score = e/w
    int cnt = 0, done = 0;

    for (int it = 0; it < NIT; it++) {
        int i = tid + it * THR;
        bool valid = (i < NQ);
        float4 x = valid ? row4[i]
                         : make_float4(NEGINF_F, NEGINF_F, NEGINF_F, NEGINF_F);
        int v0 = lo + 4 * i;
        #pragma unroll
        for (int j = 0; j < 4; j++) {
            float xv = (j == 0) ? x.x : (j == 1) ? x.y : (j == 2) ? x.z : x.w;
            bool kept = (xv >= xGT) || ((xv >= xEq) && ((v0 + j) >= tieMin));  // -inf pad -> false
            float e = kept ? __expf(xv * rcp - smax) : 0.f;
            keptE += e;
            if (!greedy) {
                unsigned mask = __ballot_sync(0xFFFFFFFFu, kept);
                if (kept) {
                    int pos = cnt + __popc(mask & ((1u << lane) - 1u));
                    ebuf[wrp][pos & 63] = e; ibuf[wrp][pos & 63] = v0 + j;
                }
                cnt += __popc(mask);
                if (cnt - done >= 32) {
                    __syncwarp();
                    int k = done + lane;
                    float e2 = ebuf[wrp][k & 63]; int i2 = ibuf[wrp][k & 63];
                    float w2 = w_at(rowbase + (unsigned)i2);
                    float lhs = e2 * bw, rhs = be * w2;
                    if (lhs > rhs || (lhs == rhs && i2 < bi)) { be = e2; bw = w2; bi = i2; }
                    done += 32;
                    __syncwarp();
                }
            }
        }
    }
    if (!greedy) {
        __syncwarp();
        int rem = cnt - done;
        if (lane < rem) {
            int k = done + lane;
            float e2 = ebuf[wrp][k & 63]; int i2 = ibuf[wrp][k & 63];
            float w2 = w_at(rowbase + (unsigned)i2);
            float lhs = e2 * bw, rhs = be * w2;
            if (lhs > rhs || (lhs == rhs && i2 < bi)) { be = e2; bw = w2; bi = i2; }
        }
    }

    __shared__ float se[THR];
    __shared__ float rbe[THR], rbw[THR];
    __shared__ int   rbi[THR];
    se[tid] = keptE; rbe[tid] = be; rbw[tid] = bw; rbi[tid] = bi;
    __syncthreads();
    for (int s2 = THR / 2; s2 > 0; s2 >>= 1) {
        if (tid < s2) {
            se[tid] += se[tid + s2];
            float lhs = rbe[tid + s2] * rbw[tid], rhs = rbe[tid] * rbw[tid + s2];
            if (lhs > rhs || (lhs == rhs && rbi[tid + s2] < rbi[tid])) {
                rbe[tid] = rbe[tid + s2]; rbw[tid] = rbw[tid + s2]; rbi[tid] = rbi[tid + s2];
            }
        }
        __syncthreads();
    }
    if (tid == 0) {
        atomicAdd(&g_keptE[b], se[0]);
        if (!greedy && rbi[0] != INT_MAX) {
            float ratio = __fdiv_rn(rbe[0], rbw[0]);
            unsigned long long pk = ((unsigned long long)okey(ratio) << 32) | (unsigned)(~rbi[0]);
            atomicMax(&g_bestPack[b], pk);
        }
    }

    // ----- last-block-per-row: finalize outputs -----
    __threadfence();
    __shared__ int s_last;
    if (tid == 0) s_last = (atomicAdd(&g_arr4[b], 1) == SEG - 1);
    __syncthreads();
    if (!s_last) return;
    if (tid == 0) {
        __threadfence();
        float logz = smax + logf(g_keptE[b]);
        const float* row = logits + (size_t)b * VOCAB;
        int tok; float lp;
        if (greedy) {
            tok = (int)(~(unsigned)(g_packMax[b] & 0xFFFFFFFFull));
            float xv = row[tok];
            bool kept = (xv >= xGT) || ((xv >= xEq) && (tok >= tieMin));
            lp = kept ? (xv * rcp - logz) : -INFINITY;
        } else {
            tok = (int)(~(unsigned)(g_bestPack[b] & 0xFFFFFFFFull));
            lp = row[tok] * rcp - logz;
        }
        out[b] = (float)tok;
        out[half_out + b] = lp;
    }
}

// ---------------- launch ----------------
extern "C" void kernel_launch(void* const* d_in, const int* in_sizes, int n_in,
                              void* d_out, int out_size) {
    const float* logits = (const float*)d_in[0];
    const float* temps  = (const float*)d_in[1];
    const float* topps  = (const float*)d_in[2];
    float* out = (float*)d_out;
    int half_out = out_size / 2;

    dim3 segGrid(SEG, BATCH);
    k0_init<<<(BATCH * 4096) / 512, 512>>>();
    kM_maxhist<<<segGrid, THR>>>(logits, temps, topps);
    k3g_gather<<<segGrid, THR>>>(logits, temps);
    k4_sample<<<segGrid, THR>>>(logits, temps, out, half_out);
}

// round 13
// speedup vs baseline: 1.2720x; 1.2720x over previous
#include <cuda_runtime.h>
#include <cstdint>
#include <climits>
#include <cfloat>
#include <math.h>

#define VOCAB 128000
#define BATCH 256
#define SEG 8
#define SEGLEN (VOCAB / SEG)          // 16000
#define THR 256
#define NQ (SEGLEN / 4)               // 4000 float4 per segment
#define NIT ((NQ + THR - 1) / THR)    // 16
#define CAP 16384
#define FINE 1024

#define NEGINF_F __int_as_float(0xFF800000)
#define POSINF_F __int_as_float(0x7F800000)

// okey-space bounds of finite floats
#define KLO 0x00800000u               // okey(-FLT_MAX)
#define KHI 0xFF800000u               // okey(FLT_MAX)+1

// ---------------- scratch ----------------
__device__ unsigned long long g_packMax[BATCH];   // (okey(x)<<32) | ~idx
__device__ float              g_hist[BATCH][4096];
__device__ int                g_B1[BATCH];
__device__ float              g_A1[BATCH];
__device__ float              g_T[BATCH];
__device__ int                g_done[BATCH];
__device__ float              g_xLo[BATCH], g_xHi[BATCH];     // raw-x interval of bin B1
__device__ int                g_candCnt[BATCH];
__device__ float              g_cs[BATCH][CAP];
__device__ int                g_ci[BATCH][CAP];
__device__ float              g_keptE[BATCH];                 // exact partial (bins > B1)
__device__ unsigned long long g_bestPack[BATCH];  // (okey(e/w)<<32) | ~idx
__device__ int                g_arrM[BATCH], g_arrG[BATCH];

// ---------------- helpers ----------------
__device__ __forceinline__ unsigned okey(float s) {
    unsigned bb = __float_as_uint(s);
    return (bb & 0x80000000u) ? ~bb : (bb | 0x80000000u);
}
__device__ __forceinline__ float okey_decode(unsigned k) {
    return __uint_as_float((k & 0x80000000u) ? (k & 0x7FFFFFFFu) : ~k);
}
__device__ __forceinline__ float bin_upper(unsigned bin) {
    return okey_decode((bin << 20) | 0x000FFFFFu);
}
__device__ __forceinline__ unsigned rotl32(unsigned x, int r) { return __funnelshift_l(x, x, r); }

// JAX partitionable threefry2x32, key (0,42): x0=0, x1=i+42, 20 rounds, bits=x0^x1.
// Returns w = -log(u), u = max(tiny, mantissa-uniform). Precise logf.
__device__ __forceinline__ float w_at(unsigned i) {
    unsigned x0 = 0u;
    unsigned x1 = i + 42u;
#define TFR(r) { x0 += x1; x1 = rotl32(x1, r); x1 ^= x0; }
    TFR(13) TFR(15) TFR(26) TFR(6)   x0 += 42u;          x1 += 0x1BD11BF1u;
    TFR(17) TFR(29) TFR(16) TFR(24)  x0 += 0x1BD11BF0u;  x1 += 2u;
    TFR(13) TFR(15) TFR(26) TFR(6)   /* +0 */            x1 += 45u;
    TFR(17) TFR(29) TFR(16) TFR(24)  x0 += 42u;          x1 += 0x1BD11BF4u;
    TFR(13) TFR(15) TFR(26) TFR(6)   x0 += 0x1BD11BF0u;  x1 += 5u;
#undef TFR
    unsigned bits = x0 ^ x1;
    float f = __uint_as_float((bits >> 9) | 0x3f800000u) - 1.0f;
    float u = fmaxf(f, 1.17549435e-38f);
    return -logf(u);
}

__device__ __forceinline__ float row_rcp(float t) {
    float tt = (t == 0.f) ? 1.f : t;
    return __fdiv_rn(1.0f, tt);
}
__device__ __forceinline__ float row_smax(int b, float rcp) {
    unsigned hk = (unsigned)(g_packMax[b] >> 32);
    return okey_decode(hk) * rcp;
}

// ---------------- K0: zero scratch ----------------
__global__ void k0_init() {
    int i = blockIdx.x * blockDim.x + threadIdx.x;   // BATCH*4096 threads
    ((float*)g_hist)[i] = 0.f;
    if (i < BATCH) {
        g_packMax[i] = 0ull; g_keptE[i] = 0.f;
        g_bestPack[i] = 0ull; g_candCnt[i] = 0;
        g_arrM[i] = 0; g_arrG[i] = 0;
    }
}

// ---------------- KM: max/argmax + bin-local-ref histogram ; last block: select + B1 preimage ----------------
__global__ void kM_maxhist(const float* __restrict__ logits, const float* __restrict__ temps,
                           const float* __restrict__ topps) {
    int b = blockIdx.y, seg = blockIdx.x, tid = threadIdx.x;
    __shared__ float h[4096];
    for (int i = tid; i < 4096; i += THR) h[i] = 0.f;
    float rcp = row_rcp(temps[b]);
    __syncthreads();
    const float4* row4 = (const float4*)(logits + (size_t)b * VOCAB + seg * SEGLEN);
    int lo = seg * SEGLEN;
    float m = -INFINITY; int mi = 0;
    for (int i = tid; i < NQ; i += THR) {
        float4 x = row4[i];
        int v = lo + 4 * i;
        #pragma unroll
        for (int j = 0; j < 4; j++) {
            float xv = (j == 0) ? x.x : (j == 1) ? x.y : (j == 2) ? x.z : x.w;
            if (xv > m) { m = xv; mi = v + j; }
            float s = xv * rcp;
            unsigned bin = okey(s) >> 20;
            float e = __expf(s - bin_upper(bin));     // bin-local reference
            atomicAdd(&h[bin], e);
        }
    }
    __shared__ unsigned long long sp[THR];
    sp[tid] = ((unsigned long long)okey(m) << 32) | (unsigned)(~mi);
    __syncthreads();
    for (int s = THR / 2; s > 0; s >>= 1) {
        if (tid < s) sp[tid] = max(sp[tid], sp[tid + s]);
        __syncthreads();
    }
    if (tid == 0) atomicMax(&g_packMax[b], sp[0]);
    for (int i = tid; i < 4096; i += THR) if (h[i] != 0.f) atomicAdd(&g_hist[b][i], h[i]);

    // ----- last-block-per-row: rescale + level-1 select + B1 raw-x preimage -----
    __threadfence();
    __shared__ int s_last;
    if (tid == 0) s_last = (atomicAdd(&g_arrM[b], 1) == SEG - 1);
    __syncthreads();
    if (!s_last) return;
    __threadfence();
    float smax = row_smax(b, rcp);
    for (int i = tid; i < 4096; i += THR) {
        float hv = g_hist[b][i];
        h[i] = (hv > 0.f) ? hv * __expf(bin_upper((unsigned)i) - smax) : 0.f;
    }
    __shared__ float warpSum[8], warpEx[8];
    __shared__ float s_T;
    __shared__ int s_seg, s_B1v;
    if (tid == 0) s_seg = THR;
    __syncthreads();
    float part = 0.f;
    #pragma unroll
    for (int jj = 0; jj < 16; jj++) part += h[4095 - (tid * 16 + jj)];
    int lane = tid & 31, wid = tid >> 5;
    float sc = part;
    for (int o = 1; o < 32; o <<= 1) { float v = __shfl_up_sync(~0u, sc, o); if (lane >= o) sc += v; }
    float ex = sc - part;
    if (lane == 31) warpSum[wid] = sc;
    __syncthreads();
    if (tid == 0) {
        float Z = 0.f;
        #pragma unroll
        for (int s = 0; s < 8; s++) Z += warpSum[s];
        float p = topps[b]; p = fminf(fmaxf(p, 0.f), 1.f);
        s_T = p * Z;
    }
    if (wid == 0) {
        float ws = (lane < 8) ? warpSum[lane] : 0.f;
        float s2 = ws;
        for (int o = 1; o < 8; o <<= 1) { float v = __shfl_up_sync(0xFFFFFFFFu, s2, o); if (lane >= o) s2 += v; }
        if (lane < 8) warpEx[lane] = s2 - ws;
    }
    __syncthreads();
    float T = s_T;
    float P = ex + warpEx[wid];
    bool flag = (part > 0.f) && (P + part > T);
    if (flag) atomicMin(&s_seg, tid);
    __syncthreads();
    if (tid == s_seg) {
        float cum = P;
        for (int jj = 0; jj < 16; jj++) {
            int bin = 4095 - (tid * 16 + jj); float hh = h[bin];
            if (hh > 0.f && cum + hh > T) { s_B1v = bin; g_A1[b] = cum; break; }
            cum += hh;
        }
    }
    __syncthreads();
    if (tid == 0) {
        g_T[b] = T;
        if (s_seg == THR) {                    // all kept
            g_done[b] = 1;
            g_xHi[b] = -FLT_MAX;               // kept path: x >= -FLT_MAX (all finite)
            g_xLo[b] = POSINF_F;               // gather never fires
        } else {
            g_done[b] = 0; g_B1[b] = s_B1v;
            int B1 = s_B1v;
            // binary search raw-x preimage of bin B1 (monotone in okey space)
            unsigned a = KLO, bnd = KHI;
            while (a < bnd) {                  // first k: bin(decode(k)*rcp) >= B1
                unsigned mid = a + (bnd - a) / 2;
                int bb = (int)(okey(okey_decode(mid) * rcp) >> 20);
                if (bb >= B1) bnd = mid; else a = mid + 1;
            }
            unsigned kA = a;
            a = kA; bnd = KHI;
            while (a < bnd) {                  // first k: bin > B1
                unsigned mid = a + (bnd - a) / 2;
                int bb = (int)(okey(okey_decode(mid) * rcp) >> 20);
                if (bb > B1) bnd = mid; else a = mid + 1;
            }
            unsigned kB = a;
            g_xLo[b] = (kA < KHI) ? okey_decode(kA) : POSINF_F;
            g_xHi[b] = (kB < KHI) ? okey_decode(kB) : POSINF_F;   // kept iff x >= xHi
        }
    }
}

// ---------------- KGS: fused scan (kept keptE+gumbel for x>=xHi, gather bin B1)
//                  last block: select2 + fine walk + candidate kept processing + outputs ----------------
__global__ void kGS_sample(const float* __restrict__ logits, const float* __restrict__ temps,
                           float* __restrict__ out, int half_out) {
    int b = blockIdx.y, seg = blockIdx.x, tid = threadIdx.x;
    int lane = tid & 31, wrp = tid >> 5;
    float t = temps[b];
    float rcp = row_rcp(t);
    float smax = row_smax(b, rcp);
    float xHi = g_xHi[b], xLo = g_xLo[b];
    bool greedy = (t == 0.f);
    const float4* row4 = (const float4*)(logits + (size_t)b * VOCAB + seg * SEGLEN);
    int lo = seg * SEGLEN;
    unsigned rowbase = (unsigned)b * (unsigned)VOCAB;

    __shared__ float h[4096];                 // multi-use: reduce arrays / hist2 / fine bufs
    __shared__ float ebuf[8][64];
    __shared__ int   ibuf[8][64];
    float keptE = 0.f;
    float be = 0.f, bw = 1.f; int bi = INT_MAX;   // best = (e, w, idx); score = e/w
    int cnt = 0, done = 0;

    for (int it = 0; it < NIT; it++) {
        int i = tid + it * THR;
        bool valid = (i < NQ);
        float4 x = valid ? row4[i]
                         : make_float4(NEGINF_F, NEGINF_F, NEGINF_F, NEGINF_F);
        int v0 = lo + 4 * i;
        #pragma unroll
        for (int j = 0; j < 4; j++) {
            float xv = (j == 0) ? x.x : (j == 1) ? x.y : (j == 2) ? x.z : x.w;
            bool kept = (xv >= xHi);                         // bins > B1: kept for sure
            float e = kept ? __expf(xv * rcp - smax) : 0.f;
            keptE += e;
            if (!greedy) {
                unsigned mask = __ballot_sync(0xFFFFFFFFu, kept);
                if (kept) {
                    int pos = cnt + __popc(mask & ((1u << lane) - 1u));
                    ebuf[wrp][pos & 63] = e; ibuf[wrp][pos & 63] = v0 + j;
                }
                cnt += __popc(mask);
                if (cnt - done >= 32) {
                    __syncwarp();
                    int k = done + lane;
                    float e2 = ebuf[wrp][k & 63]; int i2 = ibuf[wrp][k & 63];
                    float w2 = w_at(rowbase + (unsigned)i2);
                    float lhs = e2 * bw, rhs = be * w2;
                    if (lhs > rhs || (lhs == rhs && i2 < bi)) { be = e2; bw = w2; bi = i2; }
                    done += 32;
                    __syncwarp();
                }
            }
            if (!kept && xv >= xLo) {                        // bin B1 member: gather
                int pos = atomicAdd(&g_candCnt[b], 1);
                if (pos < CAP) { g_cs[b][pos] = xv * rcp; g_ci[b][pos] = v0 + j; }
            }
        }
    }
    if (!greedy) {
        __syncwarp();
        int rem = cnt - done;
        if (lane < rem) {
            int k = done + lane;
            float e2 = ebuf[wrp][k & 63]; int i2 = ibuf[wrp][k & 63];
            float w2 = w_at(rowbase + (unsigned)i2);
            float lhs = e2 * bw, rhs = be * w2;
            if (lhs > rhs || (lhs == rhs && i2 < bi)) { be = e2; bw = w2; bi = i2; }
        }
    }

    // block reduce (alias reduce arrays into h)
    {
        float* se  = h;
        float* rbe = h + 1024;
        float* rbw = h + 2048;
        int*   rbi = (int*)(h + 3072);
        se[tid] = keptE; rbe[tid] = be; rbw[tid] = bw; rbi[tid] = bi;
        __syncthreads();
        for (int s2 = THR / 2; s2 > 0; s2 >>= 1) {
            if (tid < s2) {
                se[tid] += se[tid + s2];
                float lhs = rbe[tid + s2] * rbw[tid], rhs = rbe[tid] * rbw[tid + s2];
                if (lhs > rhs || (lhs == rhs && rbi[tid + s2] < rbi[tid])) {
                    rbe[tid] = rbe[tid + s2]; rbw[tid] = rbw[tid + s2]; rbi[tid] = rbi[tid + s2];
                }
            }
            __syncthreads();
        }
        if (tid == 0) {
            atomicAdd(&g_keptE[b], se[0]);
            if (!greedy && rbi[0] != INT_MAX) {
                float ratio = __fdiv_rn(rbe[0], rbw[0]);
                unsigned long long pk = ((unsigned long long)okey(ratio) << 32) | (unsigned)(~rbi[0]);
                atomicMax(&g_bestPack[b], pk);
            }
        }
        __syncthreads();
    }

    // ----- last-block-per-row: select2 + fine walk + candidate kept processing + outputs -----
    __threadfence();
    __shared__ int s_last;
    if (tid == 0) s_last = (atomicAdd(&g_arrG[b], 1) == SEG - 1);
    __syncthreads();
    if (!s_last) return;
    __threadfence();

    int doneF = g_done[b];
    __shared__ float s_vb;
    __shared__ int   s_tm;
    float ce = 0.f;
    float be2 = 0.f, bw2 = 1.f; int bi2 = INT_MAX;
    int n = doneF ? 0 : min(g_candCnt[b], CAP);

    if (!doneF) {
        __shared__ float warpSum[8], warpEx[8];
        __shared__ int s_seg, s_B2;
        __shared__ float s_A2;
        __shared__ int   s_fcnt;
        for (int i = tid; i < 4096; i += THR) h[i] = 0.f;
        if (tid == 0) { s_fcnt = 0; s_seg = THR; }
        __syncthreads();
        for (int i = tid; i < n; i += THR) {
            float s = g_cs[b][i];
            atomicAdd(&h[(okey(s) >> 8) & 0xFFFu], __expf(s - smax));
        }
        __syncthreads();
        float T = g_T[b], A1 = g_A1[b];
        float part = 0.f;
        #pragma unroll
        for (int jj = 0; jj < 16; jj++) part += h[4095 - (tid * 16 + jj)];
        float sc = part;
        for (int o = 1; o < 32; o <<= 1) { float v = __shfl_up_sync(~0u, sc, o); if (lane >= o) sc += v; }
        float ex = sc - part;
        if (lane == 31) warpSum[wrp] = sc;
        __syncthreads();
        if (wrp == 0) {
            float ws = (lane < 8) ? warpSum[lane] : 0.f;
            float s2 = ws;
            for (int o = 1; o < 8; o <<= 1) { float v = __shfl_up_sync(0xFFFFFFFFu, s2, o); if (lane >= o) s2 += v; }
            if (lane < 8) warpEx[lane] = s2 - ws;
        }
        __syncthreads();
        float P = A1 + ex + warpEx[wrp];
        bool flag = (part > 0.f) && (P + part > T);
        if (flag) atomicMin(&s_seg, tid);
        __syncthreads();
        if (tid == s_seg) {
            float cum = P;
            for (int jj = 0; jj < 16; jj++) {
                int bin = 4095 - (tid * 16 + jj); float hh = h[bin];
                if (hh > 0.f && cum + hh > T) { s_B2 = bin; s_A2 = cum; break; }
                cum += hh;
            }
        }
        if (tid == 0 && s_seg == THR) {   // rounding edge: lowest nonempty sub-bin
            float cum = A1; int last = -1; float lastA = A1;
            for (int j = 0; j < 4096; j++) {
                int bin = 4095 - j; float hh = h[bin];
                if (hh > 0.f) { last = bin; lastA = cum; }
                cum += hh;
            }
            s_B2 = last; s_A2 = lastA;
        }
        __syncthreads();
        unsigned pref = ((unsigned)g_B1[b] << 12) | (unsigned)s_B2;
        float A2 = s_A2;
        // overlay fine buffers into h (histogram no longer needed)
        float* fs = h;
        int*   fi = (int*)(h + 1024);
        __syncthreads();
        for (int i = tid; i < n; i += THR) {
            float s = g_cs[b][i];
            if ((okey(s) >> 8) == pref) {
                int pos = atomicAdd(&s_fcnt, 1);
                if (pos < FINE) { fs[pos] = s; fi[pos] = g_ci[b][i]; }
            }
        }
        __syncthreads();
        if (tid == 0) {
            int m = min(s_fcnt, FINE);
            for (int i = 1; i < m; i++) {       // desc by (value desc, index desc)
                float sv = fs[i]; int iv = fi[i]; int j = i - 1;
                while (j >= 0 && (fs[j] < sv || (fs[j] == sv && fi[j] < iv))) {
                    fs[j + 1] = fs[j]; fi[j + 1] = fi[j]; j--;
                }
                fs[j + 1] = sv; fi[j + 1] = iv;
            }
            bool globalFirst = (A2 == 0.f);     // rank-0 always kept
            float cum = A2; int lastKept = -1;
            for (int i = 0; i < m; i++) {
                cum += __expf(fs[i] - smax);
                bool kept = (cum <= T) || (globalFirst && i == 0);
                if (kept) lastKept = i; else break;
            }
            if (lastKept < 0) {
                s_vb = fs[0]; s_tm = INT_MAX;
            } else {
                float vL = fs[lastKept];
                bool partial = (lastKept + 1 < m) && (fs[lastKept + 1] == vL);
                s_vb = vL;
                s_tm = partial ? fi[lastKept] : INT_MIN;
            }
        }
        __syncthreads();
        float vb = s_vb; int tieMin = s_tm;
        // candidate kept processing (bin-B1 members)
        for (int i = tid; i < n; i += THR) {
            float s = g_cs[b][i]; int idx = g_ci[b][i];
            bool k2 = (s > vb) || (s == vb && idx >= tieMin);
            if (k2) {
                float e = __expf(s - smax);
                ce += e;
                if (!greedy) {
                    float w = w_at(rowbase + (unsigned)idx);
                    float lhs = e * bw2, rhs = be2 * w;
                    if (lhs > rhs || (lhs == rhs && idx < bi2)) { be2 = e; bw2 = w; bi2 = idx; }
                }
            }
        }
        __syncthreads();
    }

    // reduce candidate results (alias into h again)
    {
        float* se  = h;
        float* rbe = h + 1024;
        float* rbw = h + 2048;
        int*   rbi = (int*)(h + 3072);
        se[tid] = ce; rbe[tid] = be2; rbw[tid] = bw2; rbi[tid] = bi2;
        __syncthreads();
        for (int s2 = THR / 2; s2 > 0; s2 >>= 1) {
            if (tid < s2) {
                se[tid] += se[tid + s2];
                float lhs = rbe[tid + s2] * rbw[tid], rhs = rbe[tid] * rbw[tid + s2];
                if (lhs > rhs || (lhs == rhs && rbi[tid + s2] < rbi[tid])) {
                    rbe[tid] = rbe[tid + s2]; rbw[tid] = rbw[tid + s2]; rbi[tid] = rbi[tid + s2];
                }
            }
            __syncthreads();
        }
        if (tid == 0) {
            float totalE = g_keptE[b] + se[0];
            unsigned long long bp = g_bestPack[b];
            if (!greedy && rbi[0] != INT_MAX) {
                float ratio = __fdiv_rn(rbe[0], rbw[0]);
                unsigned long long pk = ((unsigned long long)okey(ratio) << 32) | (unsigned)(~rbi[0]);
                bp = max(bp, pk);
            }
            float logz = smax + logf(totalE);
            const float* row = logits + (size_t)b * VOCAB;
            int tok; float lp;
            if (greedy) {
                tok = (int)(~(unsigned)(g_packMax[b] & 0xFFFFFFFFull));
                float xv = row[tok];
                float s = xv * rcp;
                bool kept = doneF || (xv >= xHi) || (s > s_vb) || (s == s_vb && tok >= s_tm);
                lp = kept ? (s - logz) : -INFINITY;
            } else {
                tok = (int)(~(unsigned)(bp & 0xFFFFFFFFull));
                lp = row[tok] * rcp - logz;
            }
            out[b] = (float)tok;
            out[half_out + b] = lp;
        }
    }
}

// ---------------- launch ----------------
extern "C" void kernel_launch(void* const* d_in, const int* in_sizes, int n_in,
                              void* d_out, int out_size) {
    const float* logits = (const float*)d_in[0];
    const float* temps  = (const float*)d_in[1];
    const float* topps  = (const float*)d_in[2];
    float* out = (float*)d_out;
    int half_out = out_size / 2;

    dim3 segGrid(SEG, BATCH);
    k0_init<<<(BATCH * 4096) / 512, 512>>>();
    kM_maxhist<<<segGrid, THR>>>(logits, temps, topps);
    kGS_sample<<<segGrid, THR>>>(logits, temps, out, half_out);
}